// round 4
// baseline (speedup 1.0000x reference)
#include <cuda_runtime.h>
#include <math.h>

#define B 16384
#define TDEC 12

// P[e][b][i] = dot(comb_W[i][0:128], enc[e][b][:]) — 12.6 MB scratch
__device__ __align__(16) float g_P[48 * B * 4];

__constant__ float cAWx[48 * 4];    // attn_W[e][0..3]
__constant__ float cAWh[48 * 32];   // attn_W[e][4..35]
__constant__ float cAb[48];
__constant__ float cWih[96 * 4];
__constant__ float cBih[96];
__constant__ float cBhh[96];
__constant__ float cCWx[16];        // comb_W[i][128..131]
__constant__ float cCb[4];
__constant__ float cFcW[32];
__constant__ float cFcb[1];

// ================= kernel 1: bandwidth-optimized P precompute =================
// 64 rows/block; lane = (row_in_group = lane>>2, quarter c = lane&3).
// Rotated-k smem reads -> conflict-free; quad shfl reduce; coalesced STG.32.
__global__ __launch_bounds__(256) void precompute_P(const float* __restrict__ enc,
                                                    const float* __restrict__ comb_W)
{
    __shared__ __align__(16) float tile[64 * 132];   // 33 float4 per row (pad)
    __shared__ __align__(16) float wT[33 * 20];      // per q: 16 floats W[i][4q+j], 80B stride

    const int tid = threadIdx.x;
    const int w = tid >> 5;
    const int lane = tid & 31;

    // stage weight table: wT[q*20 + i*4 + j] = comb_W[i*132 + 4q + j], q in [0,32)
    for (int idx = tid; idx < 512; idx += 256) {
        int q = idx >> 4, i = (idx >> 2) & 3, j = idx & 3;
        wT[q * 20 + i * 4 + j] = comb_W[i * 132 + q * 4 + j];
    }

    const int row0 = blockIdx.x * 64;                 // 64 rows, same e (64 | 16384)
    const float4* ebase = (const float4*)enc;
#pragma unroll
    for (int r = 0; r < 8; r++) {
        int row = row0 + w * 8 + r;
        float4 v = ebase[(size_t)row * 32 + lane];    // coalesced 512B per row
        *(float4*)&tile[(w * 8 + r) * 132 + lane * 4] = v;
    }
    __syncthreads();

    const int rl = w * 8 + (lane >> 2);               // local row
    const int c = lane & 3;                           // dim quarter [32c,32c+32)
    float s0 = 0.f, s1 = 0.f, s2 = 0.f, s3 = 0.f;
#pragma unroll
    for (int k = 0; k < 8; k++) {
        int kp = (k + 2 * c) & 7;                     // rotation: conflict-free phases
        int q = 8 * c + kp;
        float4 v  = *(const float4*)&tile[rl * 132 + q * 4];
        float4 w0 = *(const float4*)&wT[q * 20 + 0];
        float4 w1 = *(const float4*)&wT[q * 20 + 4];
        float4 w2 = *(const float4*)&wT[q * 20 + 8];
        float4 w3 = *(const float4*)&wT[q * 20 + 12];
        s0 = fmaf(v.x, w0.x, s0); s0 = fmaf(v.y, w0.y, s0); s0 = fmaf(v.z, w0.z, s0); s0 = fmaf(v.w, w0.w, s0);
        s1 = fmaf(v.x, w1.x, s1); s1 = fmaf(v.y, w1.y, s1); s1 = fmaf(v.z, w1.z, s1); s1 = fmaf(v.w, w1.w, s1);
        s2 = fmaf(v.x, w2.x, s2); s2 = fmaf(v.y, w2.y, s2); s2 = fmaf(v.z, w2.z, s2); s2 = fmaf(v.w, w2.w, s2);
        s3 = fmaf(v.x, w3.x, s3); s3 = fmaf(v.y, w3.y, s3); s3 = fmaf(v.z, w3.z, s3); s3 = fmaf(v.w, w3.w, s3);
    }
    // quad reduce (offsets 1,2): every lane in quad gets all 4 totals
    s0 += __shfl_xor_sync(0xffffffffu, s0, 1); s0 += __shfl_xor_sync(0xffffffffu, s0, 2);
    s1 += __shfl_xor_sync(0xffffffffu, s1, 1); s1 += __shfl_xor_sync(0xffffffffu, s1, 2);
    s2 += __shfl_xor_sync(0xffffffffu, s2, 1); s2 += __shfl_xor_sync(0xffffffffu, s2, 2);
    s3 += __shfl_xor_sync(0xffffffffu, s3, 1); s3 += __shfl_xor_sync(0xffffffffu, s3, 2);

    float v = s0;
    if (c == 1) v = s1; else if (c == 2) v = s2; else if (c == 3) v = s3;
    // flat float index = (row0+rl)*4 + c = row0*4 + w*32 + lane  -> coalesced 128B/warp
    g_P[(size_t)row0 * 4 + w * 32 + lane] = v;
}

// ================= kernel 2: t-loop, 8 warps / 32 elements =================
__device__ __forceinline__ float nfix(float v) {
    if (isnan(v)) return 0.f;
    return fminf(fmaxf(v, -3.4028234663852886e38f), 3.4028234663852886e38f);
}
__device__ __forceinline__ float fsigmoid(float s) {
    s = fminf(fmaxf(s, -30.f), 30.f);
    return __fdividef(1.f, 1.f + __expf(-s));
}
__device__ __forceinline__ float ftanh(float a) {
    a = fminf(fmaxf(a, -15.f), 15.f);
    float t = __expf(2.f * a);
    return 1.f - __fdividef(2.f, t + 1.f);
}

__global__ __launch_bounds__(256, 3)
void decoder_loop(const float* __restrict__ y,
                  const float* __restrict__ hidden,
                  const float* __restrict__ w_hh,
                  float* __restrict__ out)
{
    __shared__ __align__(16) float4 P_sm[48][32];   // 24576 B
    __shared__ float whh_s[96 * 32];                // 12288 B
    __shared__ float h_sm[32][33];                  // 4224 B
    __shared__ __align__(16) float4 cpart[8][32];   // 4096 B
    __shared__ float pmax[8][32];
    __shared__ float psum[8][32];
    __shared__ float opart[8][32];

    const int tid = threadIdx.x;
    const int w = tid >> 5;
    const int lane = tid & 31;
    const int b0 = blockIdx.x * 32;
    const int b = b0 + lane;

    for (int i = tid; i < 96 * 32; i += 256) whh_s[i] = w_hh[i];
    for (int i = tid; i < 32 * 32; i += 256) {
        int eb = i >> 5, j = i & 31;
        h_sm[j][eb] = hidden[(size_t)(b0 + eb) * 32 + j];
    }
    {
        const float4* gP4 = (const float4*)g_P;
        for (int i = tid; i < 48 * 32; i += 256) {
            int e = i >> 5, bl = i & 31;
            P_sm[e][bl] = __ldg(&gP4[(size_t)e * B + b0 + bl]);
        }
    }
    __syncthreads();

    float h[32];
#pragma unroll
    for (int j = 0; j < 32; j++) h[j] = h_sm[j][lane];

    float4 yv = *(const float4*)(y + (size_t)b * 52);
    float xA = nfix(yv.x), xB = nfix(yv.y), xC = nfix(yv.z), xD = nfix(yv.w);

    for (int t = 0; t < TDEC; t++) {
        // ---- phase 1: warp w -> logits e in [6w, 6w+6) ----
        float le[6];
        float mx = -3.4e38f;
#pragma unroll
        for (int j = 0; j < 6; j++) {
            const int e = 6 * w + j;
            float4 wx = *(const float4*)&cAWx[e * 4];
            float acc = cAb[e];
            acc = fmaf(xA, wx.x, acc); acc = fmaf(xB, wx.y, acc);
            acc = fmaf(xC, wx.z, acc); acc = fmaf(xD, wx.w, acc);
            const float4* wh4 = (const float4*)&cAWh[e * 32];
#pragma unroll
            for (int q = 0; q < 8; q++) {
                float4 wv = wh4[q];
                acc = fmaf(h[4 * q + 0], wv.x, acc);
                acc = fmaf(h[4 * q + 1], wv.y, acc);
                acc = fmaf(h[4 * q + 2], wv.z, acc);
                acc = fmaf(h[4 * q + 3], wv.w, acc);
            }
            le[j] = acc;
            mx = fmaxf(mx, acc);
        }
        pmax[w][lane] = mx;
        __syncthreads();   // B1

        // ---- phase 2: exp + partial ctx over own e-range ----
        float m = pmax[0][lane];
#pragma unroll
        for (int q = 1; q < 8; q++) m = fmaxf(m, pmax[q][lane]);
        float s = 0.f, c0 = 0.f, c1 = 0.f, c2 = 0.f, c3 = 0.f;
#pragma unroll
        for (int j = 0; j < 6; j++) {
            float ev = __expf(le[j] - m);
            s += ev;
            float4 p = P_sm[6 * w + j][lane];
            c0 = fmaf(ev, p.x, c0); c1 = fmaf(ev, p.y, c1);
            c2 = fmaf(ev, p.z, c2); c3 = fmaf(ev, p.w, c3);
        }
        psum[w][lane] = s;
        cpart[w][lane] = make_float4(c0, c1, c2, c3);
        __syncthreads();   // B2

        // ---- phase 3: X (redundant per warp) + GRU rows g in [4w, 4w+4) ----
        float S = 0.f, cs0 = 0.f, cs1 = 0.f, cs2 = 0.f, cs3 = 0.f;
#pragma unroll
        for (int q = 0; q < 8; q++) {
            S += psum[q][lane];
            float4 qq = cpart[q][lane];
            cs0 += qq.x; cs1 += qq.y; cs2 += qq.z; cs3 += qq.w;
        }
        float inv = __fdividef(1.f, S);
        float4 cw0 = *(const float4*)&cCWx[0];
        float4 cw1 = *(const float4*)&cCWx[4];
        float4 cw2 = *(const float4*)&cCWx[8];
        float4 cw3 = *(const float4*)&cCWx[12];
        float X0 = fmaf(cs0, inv, cCb[0]);
        X0 = fmaf(xA, cw0.x, X0); X0 = fmaf(xB, cw0.y, X0); X0 = fmaf(xC, cw0.z, X0); X0 = fmaf(xD, cw0.w, X0);
        float X1 = fmaf(cs1, inv, cCb[1]);
        X1 = fmaf(xA, cw1.x, X1); X1 = fmaf(xB, cw1.y, X1); X1 = fmaf(xC, cw1.z, X1); X1 = fmaf(xD, cw1.w, X1);
        float X2 = fmaf(cs2, inv, cCb[2]);
        X2 = fmaf(xA, cw2.x, X2); X2 = fmaf(xB, cw2.y, X2); X2 = fmaf(xC, cw2.z, X2); X2 = fmaf(xD, cw2.w, X2);
        float X3 = fmaf(cs3, inv, cCb[3]);
        X3 = fmaf(xA, cw3.x, X3); X3 = fmaf(xB, cw3.y, X3); X3 = fmaf(xC, cw3.z, X3); X3 = fmaf(xD, cw3.w, X3);

        float po = 0.f;
#pragma unroll
        for (int k = 0; k < 4; k++) {
            const int g = 4 * w + k;
            float hg = h_sm[g][lane];

            float4 wir = *(const float4*)&cWih[g * 4];
            float sr = cBih[g] + cBhh[g];
            sr = fmaf(X0, wir.x, sr); sr = fmaf(X1, wir.y, sr);
            sr = fmaf(X2, wir.z, sr); sr = fmaf(X3, wir.w, sr);
            const float4* whr = (const float4*)&whh_s[g * 32];
#pragma unroll
            for (int q = 0; q < 8; q++) {
                float4 wv = whr[q];
                sr = fmaf(h[4 * q + 0], wv.x, sr); sr = fmaf(h[4 * q + 1], wv.y, sr);
                sr = fmaf(h[4 * q + 2], wv.z, sr); sr = fmaf(h[4 * q + 3], wv.w, sr);
            }

            float4 wiz = *(const float4*)&cWih[(32 + g) * 4];
            float sz = cBih[32 + g] + cBhh[32 + g];
            sz = fmaf(X0, wiz.x, sz); sz = fmaf(X1, wiz.y, sz);
            sz = fmaf(X2, wiz.z, sz); sz = fmaf(X3, wiz.w, sz);
            const float4* whz = (const float4*)&whh_s[(32 + g) * 32];
#pragma unroll
            for (int q = 0; q < 8; q++) {
                float4 wv = whz[q];
                sz = fmaf(h[4 * q + 0], wv.x, sz); sz = fmaf(h[4 * q + 1], wv.y, sz);
                sz = fmaf(h[4 * q + 2], wv.z, sz); sz = fmaf(h[4 * q + 3], wv.w, sz);
            }

            float4 win = *(const float4*)&cWih[(64 + g) * 4];
            float gin = cBih[64 + g];
            gin = fmaf(X0, win.x, gin); gin = fmaf(X1, win.y, gin);
            gin = fmaf(X2, win.z, gin); gin = fmaf(X3, win.w, gin);
            const float4* whn = (const float4*)&whh_s[(64 + g) * 32];
            float ghn = cBhh[64 + g];
#pragma unroll
            for (int q = 0; q < 8; q++) {
                float4 wv = whn[q];
                ghn = fmaf(h[4 * q + 0], wv.x, ghn); ghn = fmaf(h[4 * q + 1], wv.y, ghn);
                ghn = fmaf(h[4 * q + 2], wv.z, ghn); ghn = fmaf(h[4 * q + 3], wv.w, ghn);
            }

            float r = fsigmoid(sr);
            float z = fsigmoid(sz);
            float n = ftanh(fmaf(r, ghn, gin));
            float hnew = fmaf(z, hg - n, n);
            h_sm[g][lane] = hnew;
            po = fmaf(hnew, cFcW[g], po);
        }
        opart[w][lane] = po;
        __syncthreads();   // B3

        // ---- phase 4: reload h, finish fc, advance x ----
        float o = cFcb[0];
#pragma unroll
        for (int q = 0; q < 8; q++) o += opart[q][lane];
#pragma unroll
        for (int j = 0; j < 32; j++) h[j] = h_sm[j][lane];
        if (w == 0) out[(size_t)t * B + b] = o;
        if (t < TDEC - 1) {
            float4 yn = *(const float4*)(y + (size_t)b * 52 + (t + 1) * 4);
            xA = yn.y; xB = yn.z; xC = yn.w; xD = o;
        }
    }
}

extern "C" void kernel_launch(void* const* d_in, const int* in_sizes, int n_in,
                              void* d_out, int out_size) {
    const float* y      = (const float*)d_in[0];
    const float* enc    = (const float*)d_in[1];
    const float* hidden = (const float*)d_in[2];
    // d_in[3] = batch_ids (unused)
    const char*  attn_W = (const char*)d_in[4];
    const float* attn_b = (const float*)d_in[5];
    const float* comb_W = (const float*)d_in[6];
    const float* comb_b = (const float*)d_in[7];
    const float* w_ih   = (const float*)d_in[8];
    const float* w_hh   = (const float*)d_in[9];
    const float* b_ih   = (const float*)d_in[10];
    const float* b_hh   = (const float*)d_in[11];
    const float* fc_W   = (const float*)d_in[12];
    const float* fc_b   = (const float*)d_in[13];

    void *pAWx, *pAWh, *pAb, *pWih, *pBih, *pBhh, *pCWx, *pCb, *pFcW, *pFcb;
    cudaGetSymbolAddress(&pAWx, cAWx);
    cudaGetSymbolAddress(&pAWh, cAWh);
    cudaGetSymbolAddress(&pAb,  cAb);
    cudaGetSymbolAddress(&pWih, cWih);
    cudaGetSymbolAddress(&pBih, cBih);
    cudaGetSymbolAddress(&pBhh, cBhh);
    cudaGetSymbolAddress(&pCWx, cCWx);
    cudaGetSymbolAddress(&pCb,  cCb);
    cudaGetSymbolAddress(&pFcW, cFcW);
    cudaGetSymbolAddress(&pFcb, cFcb);

    cudaMemcpy2DAsync(pAWx, 16, attn_W, 144, 16, 48, cudaMemcpyDeviceToDevice, 0);
    cudaMemcpy2DAsync(pAWh, 128, attn_W + 16, 144, 128, 48, cudaMemcpyDeviceToDevice, 0);
    cudaMemcpy2DAsync(pCWx, 16, (const char*)comb_W + 512, 528, 16, 4, cudaMemcpyDeviceToDevice, 0);
    cudaMemcpyAsync(pAb,  attn_b, 48 * 4,  cudaMemcpyDeviceToDevice, 0);
    cudaMemcpyAsync(pWih, w_ih, 96 * 4 * 4, cudaMemcpyDeviceToDevice, 0);
    cudaMemcpyAsync(pBih, b_ih, 96 * 4, cudaMemcpyDeviceToDevice, 0);
    cudaMemcpyAsync(pBhh, b_hh, 96 * 4, cudaMemcpyDeviceToDevice, 0);
    cudaMemcpyAsync(pCb,  comb_b, 4 * 4, cudaMemcpyDeviceToDevice, 0);
    cudaMemcpyAsync(pFcW, fc_W, 32 * 4, cudaMemcpyDeviceToDevice, 0);
    cudaMemcpyAsync(pFcb, fc_b, 4, cudaMemcpyDeviceToDevice, 0);

    precompute_P<<<(48 * B) / 64, 256>>>(enc, comb_W);
    decoder_loop<<<B / 32, 256>>>(y, hidden, w_hh, (float*)d_out);
}

// round 5
// speedup vs baseline: 1.4029x; 1.4029x over previous
#include <cuda_runtime.h>
#include <math.h>

#define B 16384
#define TDEC 12

// P[e][b][i] = dot(comb_W[i][0:128], enc[e][b][:]) — 12.6 MB scratch (L2-resident)
__device__ __align__(16) float g_P[48 * B * 4];

// ================= kernel 1: register-resident P precompute (DRAM-bound) ======
// warp = 8 rows; 8 lanes per row (sub=lane&7 covers dims [16*sub,16*sub+16)),
// row = lane>>3 handles rows base+row and base+row+4. 8 LDG.128 in flight.
__global__ __launch_bounds__(256) void precompute_P(const float* __restrict__ enc,
                                                    const float* __restrict__ comb_W)
{
    __shared__ float wsm[528];
    for (int i = threadIdx.x; i < 528; i += 256) wsm[i] = comb_W[i];
    __syncthreads();

    const int lane = threadIdx.x & 31;
    const int w = threadIdx.x >> 5;
    const int sub = lane & 7;
    const int row = lane >> 3;

    float w0[16], w1[16], w2[16], w3[16];
#pragma unroll
    for (int k = 0; k < 16; k++) {
        w0[k] = wsm[0 * 132 + sub * 16 + k];
        w1[k] = wsm[1 * 132 + sub * 16 + k];
        w2[k] = wsm[2 * 132 + sub * 16 + k];
        w3[k] = wsm[3 * 132 + sub * 16 + k];
    }

    const size_t base = (size_t)blockIdx.x * 64 + w * 8;
    const size_t R0 = base + row;        // rows R0 and R0+4
    const float4* e4 = (const float4*)enc;

    float4 v[4], u[4];
#pragma unroll
    for (int k4 = 0; k4 < 4; k4++) v[k4] = e4[R0 * 32 + sub * 4 + k4];
#pragma unroll
    for (int k4 = 0; k4 < 4; k4++) u[k4] = e4[(R0 + 4) * 32 + sub * 4 + k4];

    float s0 = 0.f, s1 = 0.f, s2 = 0.f, s3 = 0.f;
    float t0 = 0.f, t1 = 0.f, t2 = 0.f, t3 = 0.f;
#pragma unroll
    for (int k4 = 0; k4 < 4; k4++) {
        float va[4] = {v[k4].x, v[k4].y, v[k4].z, v[k4].w};
        float ua[4] = {u[k4].x, u[k4].y, u[k4].z, u[k4].w};
#pragma unroll
        for (int j = 0; j < 4; j++) {
            int k = k4 * 4 + j;
            s0 = fmaf(va[j], w0[k], s0); s1 = fmaf(va[j], w1[k], s1);
            s2 = fmaf(va[j], w2[k], s2); s3 = fmaf(va[j], w3[k], s3);
            t0 = fmaf(ua[j], w0[k], t0); t1 = fmaf(ua[j], w1[k], t1);
            t2 = fmaf(ua[j], w2[k], t2); t3 = fmaf(ua[j], w3[k], t3);
        }
    }
#pragma unroll
    for (int o = 1; o <= 4; o <<= 1) {
        s0 += __shfl_xor_sync(0xffffffffu, s0, o);
        s1 += __shfl_xor_sync(0xffffffffu, s1, o);
        s2 += __shfl_xor_sync(0xffffffffu, s2, o);
        s3 += __shfl_xor_sync(0xffffffffu, s3, o);
        t0 += __shfl_xor_sync(0xffffffffu, t0, o);
        t1 += __shfl_xor_sync(0xffffffffu, t1, o);
        t2 += __shfl_xor_sync(0xffffffffu, t2, o);
        t3 += __shfl_xor_sync(0xffffffffu, t3, o);
    }
    float sv = s0, tv = t0;
    if (sub == 1) { sv = s1; tv = t1; }
    else if (sub == 2) { sv = s2; tv = t2; }
    else if (sub == 3) { sv = s3; tv = t3; }
    if (sub < 4) {
        g_P[R0 * 4 + sub] = sv;
        g_P[(R0 + 4) * 4 + sub] = tv;
    }
}

// ================= kernel 2: barrier-free decoder, 4 sub-lanes/element ========
__device__ __forceinline__ float nfix(float v) {
    if (isnan(v)) return 0.f;
    return fminf(fmaxf(v, -3.4028234663852886e38f), 3.4028234663852886e38f);
}
__device__ __forceinline__ float fsigmoid(float s) {
    s = fminf(fmaxf(s, -30.f), 30.f);
    return __fdividef(1.f, 1.f + __expf(-s));
}
__device__ __forceinline__ float ftanh(float a) {
    a = fminf(fmaxf(a, -15.f), 15.f);
    float t = __expf(2.f * a);
    return 1.f - __fdividef(2.f, t + 1.f);
}

// smem float offsets
#define AW_OFF   0        // attn_W raw [48][36]
#define AB_OFF   1728     // attn_b [48]
#define WHH_OFF  1776     // w_hh [96][32], float4-slot rotated by row
#define WIH_OFF  4848     // w_ih [96][4]
#define BIH_OFF  5232
#define BHH_OFF  5328
#define CWX_OFF  5424     // comb_W[i][128..131]
#define CB_OFF   5440
#define FCW_OFF  5444
#define FCB_OFF  5476
#define P_OFF    5504     // P[e][bl] float4, e<48, bl<64
#define SMEM_FLOATS (5504 + 48 * 64 * 4)

__global__ __launch_bounds__(256, 2)
void decoder_loop(const float* __restrict__ y,
                  const float* __restrict__ hidden,
                  const float* __restrict__ attn_W, const float* __restrict__ attn_b,
                  const float* __restrict__ comb_W, const float* __restrict__ comb_b,
                  const float* __restrict__ w_ih, const float* __restrict__ w_hh,
                  const float* __restrict__ b_ih, const float* __restrict__ b_hh,
                  const float* __restrict__ fc_W, const float* __restrict__ fc_b,
                  float* __restrict__ out)
{
    extern __shared__ __align__(16) float dsm[];
    const int tid = threadIdx.x;
    const int w = tid >> 5;
    const int lane = tid & 31;
    const int s = lane >> 3;          // sub 0..3
    const int el = lane & 7;          // element within warp
    const int b0blk = blockIdx.x * 64;
    const int b = b0blk + w * 8 + el;

    // ---- stage weights ----
    for (int i = tid; i < 1728; i += 256) dsm[AW_OFF + i] = attn_W[i];
    if (tid < 48) dsm[AB_OFF + tid] = attn_b[tid];
    for (int i = tid; i < 3072; i += 256) {
        int g = i >> 5, j = i & 31, q = j >> 2, r = j & 3;
        dsm[WHH_OFF + g * 32 + (((q + g) & 7) << 2) + r] = w_hh[i];
    }
    for (int i = tid; i < 384; i += 256) dsm[WIH_OFF + i] = w_ih[i];
    if (tid < 96) { dsm[BIH_OFF + tid] = b_ih[tid]; dsm[BHH_OFF + tid] = b_hh[tid]; }
    if (tid < 16) dsm[CWX_OFF + tid] = comb_W[(tid >> 2) * 132 + 128 + (tid & 3)];
    if (tid < 4) dsm[CB_OFF + tid] = comb_b[tid];
    if (tid < 32) dsm[FCW_OFF + tid] = fc_W[tid];
    if (tid == 0) dsm[FCB_OFF] = fc_b[0];
    // stage P slice for this block's 64 elements
    {
        float4* Pd = (float4*)&dsm[P_OFF];
        const float4* gP4 = (const float4*)g_P;
        for (int i = tid; i < 48 * 64; i += 256) {
            int e = i >> 6, bl = i & 63;
            Pd[i] = __ldg(&gP4[(size_t)e * B + b0blk + bl]);
        }
    }
    __syncthreads();   // ONLY barrier

    // ---- per-lane state ----
    float h[32];
#pragma unroll
    for (int q = 0; q < 8; q++) {
        float4 hv = *(const float4*)(hidden + (size_t)b * 32 + 4 * q);
        h[4 * q + 0] = hv.x; h[4 * q + 1] = hv.y; h[4 * q + 2] = hv.z; h[4 * q + 3] = hv.w;
    }
    float hn[8];
#pragma unroll
    for (int k = 0; k < 8; k++) hn[k] = hidden[(size_t)b * 32 + 4 * k + s];

    float4 yv = *(const float4*)(y + (size_t)b * 52);
    float xA = nfix(yv.x), xB = nfix(yv.y), xC = nfix(yv.z), xD = nfix(yv.w);

    const float4* Pw = (const float4*)&dsm[P_OFF];
    const int pcol = w * 8 + el;

    for (int t = 0; t < TDEC; t++) {
        // ---- attn logits: sub s -> rows e = 4j+s ----
        float le[12];
        float mx = -3.4e38f;
#pragma unroll
        for (int j = 0; j < 12; j++) {
            const int e = 4 * j + s;
            const float* awr = &dsm[AW_OFF + e * 36];
            float4 wx = *(const float4*)awr;
            float acc = dsm[AB_OFF + e];
            acc = fmaf(xA, wx.x, acc); acc = fmaf(xB, wx.y, acc);
            acc = fmaf(xC, wx.z, acc); acc = fmaf(xD, wx.w, acc);
#pragma unroll
            for (int q = 0; q < 8; q++) {
                float4 wv = *(const float4*)(awr + 4 + 4 * q);
                acc = fmaf(h[4 * q + 0], wv.x, acc);
                acc = fmaf(h[4 * q + 1], wv.y, acc);
                acc = fmaf(h[4 * q + 2], wv.z, acc);
                acc = fmaf(h[4 * q + 3], wv.w, acc);
            }
            le[j] = acc;
            mx = fmaxf(mx, acc);
        }
        mx = fmaxf(mx, __shfl_xor_sync(0xffffffffu, mx, 8));
        mx = fmaxf(mx, __shfl_xor_sync(0xffffffffu, mx, 16));

        // ---- exp + ctx partials (P from smem) ----
        float ss = 0.f, c0 = 0.f, c1 = 0.f, c2 = 0.f, c3 = 0.f;
#pragma unroll
        for (int j = 0; j < 12; j++) {
            float ev = __expf(le[j] - mx);
            ss += ev;
            float4 p = Pw[(4 * j + s) * 64 + pcol];
            c0 = fmaf(ev, p.x, c0); c1 = fmaf(ev, p.y, c1);
            c2 = fmaf(ev, p.z, c2); c3 = fmaf(ev, p.w, c3);
        }
        ss += __shfl_xor_sync(0xffffffffu, ss, 8);
        ss += __shfl_xor_sync(0xffffffffu, ss, 16);
        c0 += __shfl_xor_sync(0xffffffffu, c0, 8);
        c0 += __shfl_xor_sync(0xffffffffu, c0, 16);
        c1 += __shfl_xor_sync(0xffffffffu, c1, 8);
        c1 += __shfl_xor_sync(0xffffffffu, c1, 16);
        c2 += __shfl_xor_sync(0xffffffffu, c2, 8);
        c2 += __shfl_xor_sync(0xffffffffu, c2, 16);
        c3 += __shfl_xor_sync(0xffffffffu, c3, 8);
        c3 += __shfl_xor_sync(0xffffffffu, c3, 16);

        // ---- X (all lanes, identical) ----
        float inv = __fdividef(1.f, ss);
        float4 cw0 = *(const float4*)&dsm[CWX_OFF + 0];
        float4 cw1 = *(const float4*)&dsm[CWX_OFF + 4];
        float4 cw2 = *(const float4*)&dsm[CWX_OFF + 8];
        float4 cw3 = *(const float4*)&dsm[CWX_OFF + 12];
        float X0 = fmaf(c0, inv, dsm[CB_OFF + 0]);
        X0 = fmaf(xA, cw0.x, X0); X0 = fmaf(xB, cw0.y, X0); X0 = fmaf(xC, cw0.z, X0); X0 = fmaf(xD, cw0.w, X0);
        float X1 = fmaf(c1, inv, dsm[CB_OFF + 1]);
        X1 = fmaf(xA, cw1.x, X1); X1 = fmaf(xB, cw1.y, X1); X1 = fmaf(xC, cw1.z, X1); X1 = fmaf(xD, cw1.w, X1);
        float X2 = fmaf(c2, inv, dsm[CB_OFF + 2]);
        X2 = fmaf(xA, cw2.x, X2); X2 = fmaf(xB, cw2.y, X2); X2 = fmaf(xC, cw2.z, X2); X2 = fmaf(xD, cw2.w, X2);
        float X3 = fmaf(c3, inv, dsm[CB_OFF + 3]);
        X3 = fmaf(xA, cw3.x, X3); X3 = fmaf(xB, cw3.y, X3); X3 = fmaf(xC, cw3.z, X3); X3 = fmaf(xD, cw3.w, X3);

        // ---- GRU rows g = 4k+s ----
        float po = 0.f;
#pragma unroll
        for (int k = 0; k < 8; k++) {
            const int g = 4 * k + s;
            const int gz = 32 + g, gn = 64 + g;

            float4 wi = *(const float4*)&dsm[WIH_OFF + g * 4];
            float sr = dsm[BIH_OFF + g] + dsm[BHH_OFF + g];
            sr = fmaf(X0, wi.x, sr); sr = fmaf(X1, wi.y, sr);
            sr = fmaf(X2, wi.z, sr); sr = fmaf(X3, wi.w, sr);
            const float* wrp = &dsm[WHH_OFF + g * 32];
#pragma unroll
            for (int q = 0; q < 8; q++) {
                float4 wv = *(const float4*)(wrp + (((q + g) & 7) << 2));
                sr = fmaf(h[4 * q + 0], wv.x, sr); sr = fmaf(h[4 * q + 1], wv.y, sr);
                sr = fmaf(h[4 * q + 2], wv.z, sr); sr = fmaf(h[4 * q + 3], wv.w, sr);
            }

            float4 wz = *(const float4*)&dsm[WIH_OFF + gz * 4];
            float sz = dsm[BIH_OFF + gz] + dsm[BHH_OFF + gz];
            sz = fmaf(X0, wz.x, sz); sz = fmaf(X1, wz.y, sz);
            sz = fmaf(X2, wz.z, sz); sz = fmaf(X3, wz.w, sz);
            const float* wzp = &dsm[WHH_OFF + gz * 32];
#pragma unroll
            for (int q = 0; q < 8; q++) {
                float4 wv = *(const float4*)(wzp + (((q + gz) & 7) << 2));
                sz = fmaf(h[4 * q + 0], wv.x, sz); sz = fmaf(h[4 * q + 1], wv.y, sz);
                sz = fmaf(h[4 * q + 2], wv.z, sz); sz = fmaf(h[4 * q + 3], wv.w, sz);
            }

            float4 wn = *(const float4*)&dsm[WIH_OFF + gn * 4];
            float gi = dsm[BIH_OFF + gn];
            gi = fmaf(X0, wn.x, gi); gi = fmaf(X1, wn.y, gi);
            gi = fmaf(X2, wn.z, gi); gi = fmaf(X3, wn.w, gi);
            const float* wnp = &dsm[WHH_OFF + gn * 32];
            float gh = dsm[BHH_OFF + gn];
#pragma unroll
            for (int q = 0; q < 8; q++) {
                float4 wv = *(const float4*)(wnp + (((q + gn) & 7) << 2));
                gh = fmaf(h[4 * q + 0], wv.x, gh); gh = fmaf(h[4 * q + 1], wv.y, gh);
                gh = fmaf(h[4 * q + 2], wv.z, gh); gh = fmaf(h[4 * q + 3], wv.w, gh);
            }

            float r = fsigmoid(sr);
            float z = fsigmoid(sz);
            float n = ftanh(fmaf(r, gh, gi));
            float hnew = fmaf(z, hn[k] - n, n);
            hn[k] = hnew;
            po = fmaf(hnew, dsm[FCW_OFF + g], po);
        }
        po += __shfl_xor_sync(0xffffffffu, po, 8);
        po += __shfl_xor_sync(0xffffffffu, po, 16);
        float o = dsm[FCB_OFF] + po;

        // ---- rebuild full h from all subs ----
#pragma unroll
        for (int j = 0; j < 32; j++)
            h[j] = __shfl_sync(0xffffffffu, hn[j >> 2], ((j & 3) << 3) | el);

        if (s == 0) out[(size_t)t * B + b] = o;
        if (t < TDEC - 1) {
            float4 yn = *(const float4*)(y + (size_t)b * 52 + (t + 1) * 4);
            xA = yn.y; xB = yn.z; xC = yn.w; xD = o;
        }
    }
}

extern "C" void kernel_launch(void* const* d_in, const int* in_sizes, int n_in,
                              void* d_out, int out_size) {
    const float* y      = (const float*)d_in[0];
    const float* enc    = (const float*)d_in[1];
    const float* hidden = (const float*)d_in[2];
    // d_in[3] = batch_ids (unused)
    const float* attn_W = (const float*)d_in[4];
    const float* attn_b = (const float*)d_in[5];
    const float* comb_W = (const float*)d_in[6];
    const float* comb_b = (const float*)d_in[7];
    const float* w_ih   = (const float*)d_in[8];
    const float* w_hh   = (const float*)d_in[9];
    const float* b_ih   = (const float*)d_in[10];
    const float* b_hh   = (const float*)d_in[11];
    const float* fc_W   = (const float*)d_in[12];
    const float* fc_b   = (const float*)d_in[13];

    const int smem_bytes = SMEM_FLOATS * 4;
    cudaFuncSetAttribute(decoder_loop, cudaFuncAttributeMaxDynamicSharedMemorySize,
                         smem_bytes);

    precompute_P<<<(48 * B) / 64, 256>>>(enc, comb_W);
    decoder_loop<<<B / 64, 256, smem_bytes>>>(y, hidden, attn_W, attn_b, comb_W,
                                              comb_b, w_ih, w_hh, b_ih, b_hh,
                                              fc_W, fc_b, (float*)d_out);
}

// round 6
// speedup vs baseline: 1.9171x; 1.3665x over previous
#include <cuda_runtime.h>
#include <math.h>

#define B 16384
#define TDEC 12

// P[e][b][i] = dot(comb_W[i][0:128], enc[e][b][:]) — 12.6 MB scratch (L2-resident)
__device__ __align__(16) float g_P[48 * B * 4];

// ================= kernel 1: smem-tile P precompute (R4 version, 114us) =======
__global__ __launch_bounds__(256) void precompute_P(const float* __restrict__ enc,
                                                    const float* __restrict__ comb_W)
{
    __shared__ __align__(16) float tile[64 * 132];
    __shared__ __align__(16) float wT[33 * 20];

    const int tid = threadIdx.x;
    const int w = tid >> 5;
    const int lane = tid & 31;

    for (int idx = tid; idx < 512; idx += 256) {
        int q = idx >> 4, i = (idx >> 2) & 3, j = idx & 3;
        wT[q * 20 + i * 4 + j] = comb_W[i * 132 + q * 4 + j];
    }

    const int row0 = blockIdx.x * 64;
    const float4* ebase = (const float4*)enc;
#pragma unroll
    for (int r = 0; r < 8; r++) {
        int row = row0 + w * 8 + r;
        float4 v = ebase[(size_t)row * 32 + lane];
        *(float4*)&tile[(w * 8 + r) * 132 + lane * 4] = v;
    }
    __syncthreads();

    const int rl = w * 8 + (lane >> 2);
    const int c = lane & 3;
    float s0 = 0.f, s1 = 0.f, s2 = 0.f, s3 = 0.f;
#pragma unroll
    for (int k = 0; k < 8; k++) {
        int kp = (k + 2 * c) & 7;
        int q = 8 * c + kp;
        float4 v  = *(const float4*)&tile[rl * 132 + q * 4];
        float4 w0 = *(const float4*)&wT[q * 20 + 0];
        float4 w1 = *(const float4*)&wT[q * 20 + 4];
        float4 w2 = *(const float4*)&wT[q * 20 + 8];
        float4 w3 = *(const float4*)&wT[q * 20 + 12];
        s0 = fmaf(v.x, w0.x, s0); s0 = fmaf(v.y, w0.y, s0); s0 = fmaf(v.z, w0.z, s0); s0 = fmaf(v.w, w0.w, s0);
        s1 = fmaf(v.x, w1.x, s1); s1 = fmaf(v.y, w1.y, s1); s1 = fmaf(v.z, w1.z, s1); s1 = fmaf(v.w, w1.w, s1);
        s2 = fmaf(v.x, w2.x, s2); s2 = fmaf(v.y, w2.y, s2); s2 = fmaf(v.z, w2.z, s2); s2 = fmaf(v.w, w2.w, s2);
        s3 = fmaf(v.x, w3.x, s3); s3 = fmaf(v.y, w3.y, s3); s3 = fmaf(v.z, w3.z, s3); s3 = fmaf(v.w, w3.w, s3);
    }
    s0 += __shfl_xor_sync(0xffffffffu, s0, 1); s0 += __shfl_xor_sync(0xffffffffu, s0, 2);
    s1 += __shfl_xor_sync(0xffffffffu, s1, 1); s1 += __shfl_xor_sync(0xffffffffu, s1, 2);
    s2 += __shfl_xor_sync(0xffffffffu, s2, 1); s2 += __shfl_xor_sync(0xffffffffu, s2, 2);
    s3 += __shfl_xor_sync(0xffffffffu, s3, 1); s3 += __shfl_xor_sync(0xffffffffu, s3, 2);

    float v = s0;
    if (c == 1) v = s1; else if (c == 2) v = s2; else if (c == 3) v = s3;
    g_P[(size_t)row0 * 4 + w * 32 + lane] = v;
}

// ================= kernel 2: barrier-free decoder, online softmax =============
__device__ __forceinline__ float nfix(float v) {
    if (isnan(v)) return 0.f;
    return fminf(fmaxf(v, -3.4028234663852886e38f), 3.4028234663852886e38f);
}
__device__ __forceinline__ float fsigmoid(float s) {
    s = fminf(fmaxf(s, -30.f), 30.f);
    return __fdividef(1.f, 1.f + __expf(-s));
}
__device__ __forceinline__ float ftanh(float a) {
    a = fminf(fmaxf(a, -15.f), 15.f);
    float t = __expf(2.f * a);
    return 1.f - __fdividef(2.f, t + 1.f);
}

#define AW_OFF   0        // attn_W raw [48][36]
#define AB_OFF   1728     // attn_b [48]
#define WHH_OFF  1776     // w_hh [96][32], float4-slot rotated by row
#define WIH_OFF  4848     // w_ih [96][4]
#define BIH_OFF  5232
#define BHH_OFF  5328
#define CWX_OFF  5424     // comb_W[i][128..131]
#define CB_OFF   5440
#define FCW_OFF  5444
#define FCB_OFF  5476
#define P_OFF    5504     // P[e][bl] float4, e<48, bl<64
#define SMEM_FLOATS (5504 + 48 * 64 * 4)

__global__ __launch_bounds__(256, 2)
void decoder_loop(const float* __restrict__ y,
                  const float* __restrict__ hidden,
                  const float* __restrict__ attn_W, const float* __restrict__ attn_b,
                  const float* __restrict__ comb_W, const float* __restrict__ comb_b,
                  const float* __restrict__ w_ih, const float* __restrict__ w_hh,
                  const float* __restrict__ b_ih, const float* __restrict__ b_hh,
                  const float* __restrict__ fc_W, const float* __restrict__ fc_b,
                  float* __restrict__ out)
{
    extern __shared__ __align__(16) float dsm[];
    const int tid = threadIdx.x;
    const int w = tid >> 5;
    const int lane = tid & 31;
    const int s = lane >> 3;          // sub 0..3
    const int el = lane & 7;          // element within warp
    const int b0blk = blockIdx.x * 64;
    const int b = b0blk + w * 8 + el;

    // ---- stage weights ----
    for (int i = tid; i < 1728; i += 256) dsm[AW_OFF + i] = attn_W[i];
    if (tid < 48) dsm[AB_OFF + tid] = attn_b[tid];
    for (int i = tid; i < 3072; i += 256) {
        int g = i >> 5, j = i & 31, q = j >> 2, r = j & 3;
        dsm[WHH_OFF + g * 32 + (((q + g) & 7) << 2) + r] = w_hh[i];
    }
    for (int i = tid; i < 384; i += 256) dsm[WIH_OFF + i] = w_ih[i];
    if (tid < 96) { dsm[BIH_OFF + tid] = b_ih[tid]; dsm[BHH_OFF + tid] = b_hh[tid]; }
    if (tid < 16) dsm[CWX_OFF + tid] = comb_W[(tid >> 2) * 132 + 128 + (tid & 3)];
    if (tid < 4) dsm[CB_OFF + tid] = comb_b[tid];
    if (tid < 32) dsm[FCW_OFF + tid] = fc_W[tid];
    if (tid == 0) dsm[FCB_OFF] = fc_b[0];
    {
        float4* Pd = (float4*)&dsm[P_OFF];
        const float4* gP4 = (const float4*)g_P;
        for (int i = tid; i < 48 * 64; i += 256) {
            int e = i >> 6, bl = i & 63;
            Pd[i] = __ldg(&gP4[(size_t)e * B + b0blk + bl]);
        }
    }
    __syncthreads();   // ONLY barrier

    // ---- per-lane state ----
    float h[32];
#pragma unroll
    for (int q = 0; q < 8; q++) {
        float4 hv = *(const float4*)(hidden + (size_t)b * 32 + 4 * q);
        h[4 * q + 0] = hv.x; h[4 * q + 1] = hv.y; h[4 * q + 2] = hv.z; h[4 * q + 3] = hv.w;
    }

    float4 yv = *(const float4*)(y + (size_t)b * 52);
    float xA = nfix(yv.x), xB = nfix(yv.y), xC = nfix(yv.z), xD = nfix(yv.w);

    const float4* Pw = (const float4*)&dsm[P_OFF];
    const int pcol = w * 8 + el;

    for (int t = 0; t < TDEC; t++) {
        // ---- fused: attn logits + online softmax + ctx (rows e = 4j+s) ----
        float m = -3.4028234663852886e38f;
        float ss = 0.f, c0 = 0.f, c1 = 0.f, c2 = 0.f, c3 = 0.f;
#pragma unroll
        for (int j = 0; j < 12; j++) {
            const int e = 4 * j + s;
            const float* awr = &dsm[AW_OFF + e * 36];
            float4 wx = *(const float4*)awr;
            float acc = dsm[AB_OFF + e];
            acc = fmaf(xA, wx.x, acc); acc = fmaf(xB, wx.y, acc);
            acc = fmaf(xC, wx.z, acc); acc = fmaf(xD, wx.w, acc);
#pragma unroll
            for (int q = 0; q < 8; q++) {
                float4 wv = *(const float4*)(awr + 4 + 4 * q);
                acc = fmaf(h[4 * q + 0], wv.x, acc);
                acc = fmaf(h[4 * q + 1], wv.y, acc);
                acc = fmaf(h[4 * q + 2], wv.z, acc);
                acc = fmaf(h[4 * q + 3], wv.w, acc);
            }
            float mn = fmaxf(m, acc);
            float f  = __expf(m - mn);      // first iter: exp(-huge) = 0
            float ev = __expf(acc - mn);
            float4 p = Pw[e * 64 + pcol];
            ss = fmaf(ss, f, ev);
            c0 = fmaf(c0, f, ev * p.x);
            c1 = fmaf(c1, f, ev * p.y);
            c2 = fmaf(c2, f, ev * p.z);
            c3 = fmaf(c3, f, ev * p.w);
            m = mn;
        }
        // ---- merge the 4 subs (offsets 8, 16) with rescale ----
#pragma unroll
        for (int o = 8; o <= 16; o <<= 1) {
            float m2 = __shfl_xor_sync(0xffffffffu, m, o);
            float s2 = __shfl_xor_sync(0xffffffffu, ss, o);
            float q0 = __shfl_xor_sync(0xffffffffu, c0, o);
            float q1 = __shfl_xor_sync(0xffffffffu, c1, o);
            float q2 = __shfl_xor_sync(0xffffffffu, c2, o);
            float q3 = __shfl_xor_sync(0xffffffffu, c3, o);
            float mn = fmaxf(m, m2);
            float f1 = __expf(m - mn);
            float f2 = __expf(m2 - mn);
            ss = ss * f1 + s2 * f2;
            c0 = c0 * f1 + q0 * f2;
            c1 = c1 * f1 + q1 * f2;
            c2 = c2 * f1 + q2 * f2;
            c3 = c3 * f1 + q3 * f2;
            m = mn;
        }

        // ---- X (all lanes, identical within element) ----
        float inv = __fdividef(1.f, ss);
        float4 cw0 = *(const float4*)&dsm[CWX_OFF + 0];
        float4 cw1 = *(const float4*)&dsm[CWX_OFF + 4];
        float4 cw2 = *(const float4*)&dsm[CWX_OFF + 8];
        float4 cw3 = *(const float4*)&dsm[CWX_OFF + 12];
        float X0 = fmaf(c0, inv, dsm[CB_OFF + 0]);
        X0 = fmaf(xA, cw0.x, X0); X0 = fmaf(xB, cw0.y, X0); X0 = fmaf(xC, cw0.z, X0); X0 = fmaf(xD, cw0.w, X0);
        float X1 = fmaf(c1, inv, dsm[CB_OFF + 1]);
        X1 = fmaf(xA, cw1.x, X1); X1 = fmaf(xB, cw1.y, X1); X1 = fmaf(xC, cw1.z, X1); X1 = fmaf(xD, cw1.w, X1);
        float X2 = fmaf(c2, inv, dsm[CB_OFF + 2]);
        X2 = fmaf(xA, cw2.x, X2); X2 = fmaf(xB, cw2.y, X2); X2 = fmaf(xC, cw2.z, X2); X2 = fmaf(xD, cw2.w, X2);
        float X3 = fmaf(c3, inv, dsm[CB_OFF + 3]);
        X3 = fmaf(xA, cw3.x, X3); X3 = fmaf(xB, cw3.y, X3); X3 = fmaf(xC, cw3.z, X3); X3 = fmaf(xD, cw3.w, X3);

        // ---- GRU rows g = 4k+s (old h[4k+s] kept in h until rebuild) ----
        float hn[8];
        float po = 0.f;
#pragma unroll
        for (int k = 0; k < 8; k++) {
            const int g = 4 * k + s;
            const int gz = 32 + g, gn = 64 + g;

            float4 wi = *(const float4*)&dsm[WIH_OFF + g * 4];
            float sr = dsm[BIH_OFF + g] + dsm[BHH_OFF + g];
            sr = fmaf(X0, wi.x, sr); sr = fmaf(X1, wi.y, sr);
            sr = fmaf(X2, wi.z, sr); sr = fmaf(X3, wi.w, sr);
            const float* wrp = &dsm[WHH_OFF + g * 32];
#pragma unroll
            for (int q = 0; q < 8; q++) {
                float4 wv = *(const float4*)(wrp + (((q + g) & 7) << 2));
                sr = fmaf(h[4 * q + 0], wv.x, sr); sr = fmaf(h[4 * q + 1], wv.y, sr);
                sr = fmaf(h[4 * q + 2], wv.z, sr); sr = fmaf(h[4 * q + 3], wv.w, sr);
            }

            float4 wz = *(const float4*)&dsm[WIH_OFF + gz * 4];
            float sz = dsm[BIH_OFF + gz] + dsm[BHH_OFF + gz];
            sz = fmaf(X0, wz.x, sz); sz = fmaf(X1, wz.y, sz);
            sz = fmaf(X2, wz.z, sz); sz = fmaf(X3, wz.w, sz);
            const float* wzp = &dsm[WHH_OFF + gz * 32];
#pragma unroll
            for (int q = 0; q < 8; q++) {
                float4 wv = *(const float4*)(wzp + (((q + gz) & 7) << 2));
                sz = fmaf(h[4 * q + 0], wv.x, sz); sz = fmaf(h[4 * q + 1], wv.y, sz);
                sz = fmaf(h[4 * q + 2], wv.z, sz); sz = fmaf(h[4 * q + 3], wv.w, sz);
            }

            float4 wn = *(const float4*)&dsm[WIH_OFF + gn * 4];
            float gi = dsm[BIH_OFF + gn];
            gi = fmaf(X0, wn.x, gi); gi = fmaf(X1, wn.y, gi);
            gi = fmaf(X2, wn.z, gi); gi = fmaf(X3, wn.w, gi);
            const float* wnp = &dsm[WHH_OFF + gn * 32];
            float gh = dsm[BHH_OFF + gn];
#pragma unroll
            for (int q = 0; q < 8; q++) {
                float4 wv = *(const float4*)(wnp + (((q + gn) & 7) << 2));
                gh = fmaf(h[4 * q + 0], wv.x, gh); gh = fmaf(h[4 * q + 1], wv.y, gh);
                gh = fmaf(h[4 * q + 2], wv.z, gh); gh = fmaf(h[4 * q + 3], wv.w, gh);
            }

            float r = fsigmoid(sr);
            float z = fsigmoid(sz);
            float n = ftanh(fmaf(r, gh, gi));
            float hnew = fmaf(z, h[4 * k + s] - n, n);
            hn[k] = hnew;
            po = fmaf(hnew, dsm[FCW_OFF + g], po);
        }
        po += __shfl_xor_sync(0xffffffffu, po, 8);
        po += __shfl_xor_sync(0xffffffffu, po, 16);
        float o = dsm[FCB_OFF] + po;

        // ---- rebuild full h from all subs ----
#pragma unroll
        for (int j = 0; j < 32; j++)
            h[j] = __shfl_sync(0xffffffffu, hn[j >> 2], ((j & 3) << 3) | el);

        if (s == 0) out[(size_t)t * B + b] = o;
        if (t < TDEC - 1) {
            float4 yn = *(const float4*)(y + (size_t)b * 52 + (t + 1) * 4);
            xA = yn.y; xB = yn.z; xC = yn.w; xD = o;
        }
    }
}

extern "C" void kernel_launch(void* const* d_in, const int* in_sizes, int n_in,
                              void* d_out, int out_size) {
    const float* y      = (const float*)d_in[0];
    const float* enc    = (const float*)d_in[1];
    const float* hidden = (const float*)d_in[2];
    // d_in[3] = batch_ids (unused)
    const float* attn_W = (const float*)d_in[4];
    const float* attn_b = (const float*)d_in[5];
    const float* comb_W = (const float*)d_in[6];
    const float* comb_b = (const float*)d_in[7];
    const float* w_ih   = (const float*)d_in[8];
    const float* w_hh   = (const float*)d_in[9];
    const float* b_ih   = (const float*)d_in[10];
    const float* b_hh   = (const float*)d_in[11];
    const float* fc_W   = (const float*)d_in[12];
    const float* fc_b   = (const float*)d_in[13];

    const int smem_bytes = SMEM_FLOATS * 4;
    cudaFuncSetAttribute(decoder_loop, cudaFuncAttributeMaxDynamicSharedMemorySize,
                         smem_bytes);

    precompute_P<<<(48 * B) / 64, 256>>>(enc, comb_W);
    decoder_loop<<<B / 64, 256, smem_bytes>>>(y, hidden, attn_W, attn_b, comb_W,
                                              comb_b, w_ih, w_hh, b_ih, b_hh,
                                              fc_W, fc_b, (float*)d_out);
}

// round 7
// speedup vs baseline: 2.4748x; 1.2909x over previous
#include <cuda_runtime.h>
#include <math.h>

#define B 16384
#define TDEC 12

typedef unsigned long long ull;

// P[e][b][i] = dot(comb_W[i][0:128], enc[e][b][:]) — 12.6 MB scratch (L2-resident)
__device__ __align__(16) float g_P[48 * B * 4];

// ---- f32x2 packed math (sm_103a) ----
__device__ __forceinline__ ull fma2(ull a, ull b, ull c) {
    ull d;
    asm("fma.rn.f32x2 %0, %1, %2, %3;" : "=l"(d) : "l"(a), "l"(b), "l"(c));
    return d;
}
__device__ __forceinline__ ull add2(ull a, ull b) {
    ull d;
    asm("add.rn.f32x2 %0, %1, %2;" : "=l"(d) : "l"(a), "l"(b));
    return d;
}
__device__ __forceinline__ ull pk2(float lo, float hi) {
    ull r;
    asm("mov.b64 %0, {%1, %2};" : "=l"(r) : "f"(lo), "f"(hi));
    return r;
}
__device__ __forceinline__ float2 upk2(ull v) {
    float2 f;
    asm("mov.b64 {%0, %1}, %2;" : "=f"(f.x), "=f"(f.y) : "l"(v));
    return f;
}

// ================= kernel 1: smem-tile P precompute =================
__global__ __launch_bounds__(256) void precompute_P(const float* __restrict__ enc,
                                                    const float* __restrict__ comb_W)
{
    __shared__ __align__(16) float tile[64 * 132];
    __shared__ __align__(16) float wT[33 * 20];

    const int tid = threadIdx.x;
    const int w = tid >> 5;
    const int lane = tid & 31;

    for (int idx = tid; idx < 512; idx += 256) {
        int q = idx >> 4, i = (idx >> 2) & 3, j = idx & 3;
        wT[q * 20 + i * 4 + j] = comb_W[i * 132 + q * 4 + j];
    }

    const int row0 = blockIdx.x * 64;
    const float4* ebase = (const float4*)enc;
#pragma unroll
    for (int r = 0; r < 8; r++) {
        int row = row0 + w * 8 + r;
        float4 v = ebase[(size_t)row * 32 + lane];
        *(float4*)&tile[(w * 8 + r) * 132 + lane * 4] = v;
    }
    __syncthreads();

    const int rl = w * 8 + (lane >> 2);
    const int c = lane & 3;
    float s0 = 0.f, s1 = 0.f, s2 = 0.f, s3 = 0.f;
#pragma unroll
    for (int k = 0; k < 8; k++) {
        int kp = (k + 2 * c) & 7;
        int q = 8 * c + kp;
        float4 v  = *(const float4*)&tile[rl * 132 + q * 4];
        float4 w0 = *(const float4*)&wT[q * 20 + 0];
        float4 w1 = *(const float4*)&wT[q * 20 + 4];
        float4 w2 = *(const float4*)&wT[q * 20 + 8];
        float4 w3 = *(const float4*)&wT[q * 20 + 12];
        s0 = fmaf(v.x, w0.x, s0); s0 = fmaf(v.y, w0.y, s0); s0 = fmaf(v.z, w0.z, s0); s0 = fmaf(v.w, w0.w, s0);
        s1 = fmaf(v.x, w1.x, s1); s1 = fmaf(v.y, w1.y, s1); s1 = fmaf(v.z, w1.z, s1); s1 = fmaf(v.w, w1.w, s1);
        s2 = fmaf(v.x, w2.x, s2); s2 = fmaf(v.y, w2.y, s2); s2 = fmaf(v.z, w2.z, s2); s2 = fmaf(v.w, w2.w, s2);
        s3 = fmaf(v.x, w3.x, s3); s3 = fmaf(v.y, w3.y, s3); s3 = fmaf(v.z, w3.z, s3); s3 = fmaf(v.w, w3.w, s3);
    }
    s0 += __shfl_xor_sync(0xffffffffu, s0, 1); s0 += __shfl_xor_sync(0xffffffffu, s0, 2);
    s1 += __shfl_xor_sync(0xffffffffu, s1, 1); s1 += __shfl_xor_sync(0xffffffffu, s1, 2);
    s2 += __shfl_xor_sync(0xffffffffu, s2, 1); s2 += __shfl_xor_sync(0xffffffffu, s2, 2);
    s3 += __shfl_xor_sync(0xffffffffu, s3, 1); s3 += __shfl_xor_sync(0xffffffffu, s3, 2);

    float v = s0;
    if (c == 1) v = s1; else if (c == 2) v = s2; else if (c == 3) v = s3;
    g_P[(size_t)row0 * 4 + w * 32 + lane] = v;
}

// ================= kernel 2: f32x2 decoder, barrier-free t-loop =============
__device__ __forceinline__ float nfix(float v) {
    if (isnan(v)) return 0.f;
    return fminf(fmaxf(v, -3.4028234663852886e38f), 3.4028234663852886e38f);
}
__device__ __forceinline__ float fsigmoid(float s) {
    s = fminf(fmaxf(s, -30.f), 30.f);
    return __fdividef(1.f, 1.f + __expf(-s));
}
__device__ __forceinline__ float ftanh(float a) {
    a = fminf(fmaxf(a, -15.f), 15.f);
    float t = __expf(2.f * a);
    return 1.f - __fdividef(2.f, t + 1.f);
}

// smem float offsets
#define AW_OFF   0        // attn_W raw [48][36]
#define AB_OFF   1728     // attn_b [48]
#define WHH_OFF  1776     // w_hh [96][32], float4-slot rotated by row
#define WIH_OFF  4848     // w_ih [96][4]
#define BRZ_OFF  5232     // b_ih[g]+b_hh[g], g<64
#define BIN_OFF  5296     // b_ih[64..96)
#define BHN_OFF  5328     // b_hh[64..96)
#define CWX_OFF  5360     // comb_W[i][128..131]
#define CB_OFF   5376
#define FCW_OFF  5380
#define FCB_OFF  5412
#define P_OFF    5424     // P[pcol][e] float4, row stride 51
#define RB_OFF   18480    // rebuild buffer: 8 warps x 8 el x 36 floats
#define SMEM_FLOATS (18480 + 8 * 288)

__global__ __launch_bounds__(256, 2)
void decoder_loop(const float* __restrict__ y,
                  const float* __restrict__ hidden,
                  const float* __restrict__ attn_W, const float* __restrict__ attn_b,
                  const float* __restrict__ comb_W, const float* __restrict__ comb_b,
                  const float* __restrict__ w_ih, const float* __restrict__ w_hh,
                  const float* __restrict__ b_ih, const float* __restrict__ b_hh,
                  const float* __restrict__ fc_W, const float* __restrict__ fc_b,
                  float* __restrict__ out)
{
    extern __shared__ __align__(16) float dsm[];
    const int tid = threadIdx.x;
    const int w = tid >> 5;
    const int lane = tid & 31;
    const int s = lane >> 3;          // sub 0..3
    const int el = lane & 7;          // element within warp
    const int b0blk = blockIdx.x * 64;
    const int b = b0blk + w * 8 + el;

    // ---- stage weights ----
    for (int i = tid; i < 1728; i += 256) dsm[AW_OFF + i] = attn_W[i];
    if (tid < 48) dsm[AB_OFF + tid] = attn_b[tid];
    for (int i = tid; i < 3072; i += 256) {
        int g = i >> 5, j = i & 31, q = j >> 2, r = j & 3;
        dsm[WHH_OFF + g * 32 + (((q + g) & 7) << 2) + r] = w_hh[i];
    }
    for (int i = tid; i < 384; i += 256) dsm[WIH_OFF + i] = w_ih[i];
    if (tid < 64) dsm[BRZ_OFF + tid] = b_ih[tid] + b_hh[tid];
    else if (tid < 96) {
        dsm[BIN_OFF + tid - 64] = b_ih[tid];
        dsm[BHN_OFF + tid - 64] = b_hh[tid];
    }
    if (tid < 16) dsm[CWX_OFF + tid] = comb_W[(tid >> 2) * 132 + 128 + (tid & 3)];
    if (tid < 4) dsm[CB_OFF + tid] = comb_b[tid];
    if (tid < 32) dsm[FCW_OFF + tid] = fc_W[tid];
    if (tid == 0) dsm[FCB_OFF] = fc_b[0];
    // stage P transposed: Pd[pcol*51 + e]
    {
        float4* Pd = (float4*)&dsm[P_OFF];
        const float4* gP4 = (const float4*)g_P;
        for (int i = tid; i < 48 * 64; i += 256) {
            int e = i >> 6, pc = i & 63;
            Pd[pc * 51 + e] = __ldg(&gP4[(size_t)e * B + b0blk + pc]);
        }
    }
    __syncthreads();   // only block barrier

    // ---- per-lane state: h packed in f32x2 pairs ----
    ull hp[16];
#pragma unroll
    for (int q = 0; q < 8; q++) {
        float4 hv = *(const float4*)(hidden + (size_t)b * 32 + 4 * q);
        hp[2 * q + 0] = pk2(hv.x, hv.y);
        hp[2 * q + 1] = pk2(hv.z, hv.w);
    }

    float4 yv = *(const float4*)(y + (size_t)b * 52);
    float xA = nfix(yv.x), xB = nfix(yv.y), xC = nfix(yv.z), xD = nfix(yv.w);

    const ulonglong2* Pw2 = (const ulonglong2*)&dsm[P_OFF];
    const int prow = (w * 8 + el) * 51;
    float* rbuf = &dsm[RB_OFF + w * 288 + el * 36];
    const ulonglong2* rb2 = (const ulonglong2*)rbuf;

    for (int t = 0; t < TDEC; t++) {
        ull xab = pk2(xA, xB), xcd = pk2(xC, xD);

        // ---- attn logits + exp + ctx (rows e = 4j+s), no max (bounded logits) ----
        float ss = 0.f;
        ull c01 = 0, c23 = 0;
#pragma unroll
        for (int j = 0; j < 12; j++) {
            const int e = 4 * j + s;
            const ulonglong2* awr2 = (const ulonglong2*)&dsm[AW_OFF + e * 36];
            ull acc2 = pk2(dsm[AB_OFF + e], 0.f);
            ulonglong2 w0 = awr2[0];
            acc2 = fma2(xab, w0.x, acc2);
            acc2 = fma2(xcd, w0.y, acc2);
#pragma unroll
            for (int q = 0; q < 8; q++) {
                ulonglong2 wv = awr2[1 + q];
                acc2 = fma2(hp[2 * q + 0], wv.x, acc2);
                acc2 = fma2(hp[2 * q + 1], wv.y, acc2);
            }
            float2 ac = upk2(acc2);
            float ev = __expf(ac.x + ac.y);
            ss += ev;
            ull evv = pk2(ev, ev);
            ulonglong2 pv = Pw2[prow + e];
            c01 = fma2(evv, pv.x, c01);
            c23 = fma2(evv, pv.y, c23);
        }
        // merge 4 subs (plain sums — no rescale needed)
#pragma unroll
        for (int o = 8; o <= 16; o <<= 1) {
            ss += __shfl_xor_sync(0xffffffffu, ss, o);
            c01 = add2(c01, __shfl_xor_sync(0xffffffffu, c01, o));
            c23 = add2(c23, __shfl_xor_sync(0xffffffffu, c23, o));
        }

        // ---- X ----
        float inv = __fdividef(1.f, ss);
        float2 cA = upk2(c01), cB = upk2(c23);
        float4 cw0 = *(const float4*)&dsm[CWX_OFF + 0];
        float4 cw1 = *(const float4*)&dsm[CWX_OFF + 4];
        float4 cw2 = *(const float4*)&dsm[CWX_OFF + 8];
        float4 cw3 = *(const float4*)&dsm[CWX_OFF + 12];
        float X0 = fmaf(cA.x, inv, dsm[CB_OFF + 0]);
        X0 = fmaf(xA, cw0.x, X0); X0 = fmaf(xB, cw0.y, X0); X0 = fmaf(xC, cw0.z, X0); X0 = fmaf(xD, cw0.w, X0);
        float X1 = fmaf(cA.y, inv, dsm[CB_OFF + 1]);
        X1 = fmaf(xA, cw1.x, X1); X1 = fmaf(xB, cw1.y, X1); X1 = fmaf(xC, cw1.z, X1); X1 = fmaf(xD, cw1.w, X1);
        float X2 = fmaf(cB.x, inv, dsm[CB_OFF + 2]);
        X2 = fmaf(xA, cw2.x, X2); X2 = fmaf(xB, cw2.y, X2); X2 = fmaf(xC, cw2.z, X2); X2 = fmaf(xD, cw2.w, X2);
        float X3 = fmaf(cB.y, inv, dsm[CB_OFF + 3]);
        X3 = fmaf(xA, cw3.x, X3); X3 = fmaf(xB, cw3.y, X3); X3 = fmaf(xC, cw3.z, X3); X3 = fmaf(xD, cw3.w, X3);
        ull X01 = pk2(X0, X1), X23 = pk2(X2, X3);

        // ---- GRU rows g = 4k+s ----
        float po = 0.f;
        const ulonglong2* wi2 = (const ulonglong2*)&dsm[WIH_OFF];
#pragma unroll
        for (int k = 0; k < 8; k++) {
            const int g = 4 * k + s;
            const int gz = 32 + g, gn = 64 + g;

            // r gate
            ulonglong2 wiv = wi2[g];
            ull a2 = fma2(X01, wiv.x, pk2(dsm[BRZ_OFF + g], 0.f));
            a2 = fma2(X23, wiv.y, a2);
            const ulonglong2* wp = (const ulonglong2*)&dsm[WHH_OFF + g * 32];
#pragma unroll
            for (int q = 0; q < 8; q++) {
                ulonglong2 wv = wp[(q + g) & 7];
                a2 = fma2(hp[2 * q + 0], wv.x, a2);
                a2 = fma2(hp[2 * q + 1], wv.y, a2);
            }
            float2 au = upk2(a2);
            float sr = au.x + au.y;

            // z gate
            ulonglong2 wzv = wi2[gz];
            ull z2 = fma2(X01, wzv.x, pk2(dsm[BRZ_OFF + gz], 0.f));
            z2 = fma2(X23, wzv.y, z2);
            const ulonglong2* wzp = (const ulonglong2*)&dsm[WHH_OFF + gz * 32];
#pragma unroll
            for (int q = 0; q < 8; q++) {
                ulonglong2 wv = wzp[(q + gz) & 7];
                z2 = fma2(hp[2 * q + 0], wv.x, z2);
                z2 = fma2(hp[2 * q + 1], wv.y, z2);
            }
            float2 zu = upk2(z2);
            float sz = zu.x + zu.y;

            // n gate: gi (input part) and gh (hidden part) separate
            ulonglong2 wnv = wi2[gn];
            ull i2 = fma2(X01, wnv.x, pk2(dsm[BIN_OFF + g], 0.f));
            i2 = fma2(X23, wnv.y, i2);
            float2 iu = upk2(i2);
            float gi = iu.x + iu.y;

            ull g2 = pk2(dsm[BHN_OFF + g], 0.f);
            const ulonglong2* wnp = (const ulonglong2*)&dsm[WHH_OFF + gn * 32];
#pragma unroll
            for (int q = 0; q < 8; q++) {
                ulonglong2 wv = wnp[(q + gn) & 7];
                g2 = fma2(hp[2 * q + 0], wv.x, g2);
                g2 = fma2(hp[2 * q + 1], wv.y, g2);
            }
            float2 gu = upk2(g2);
            float gh = gu.x + gu.y;

            float r = fsigmoid(sr);
            float z = fsigmoid(sz);
            float n = ftanh(fmaf(r, gh, gi));
            float2 hpair = upk2(hp[2 * k + (s >> 1)]);
            float hold = (s & 1) ? hpair.y : hpair.x;
            float hnew = fmaf(z, hold - n, n);
            rbuf[g] = hnew;
            po = fmaf(hnew, dsm[FCW_OFF + g], po);
        }
        po += __shfl_xor_sync(0xffffffffu, po, 8);
        po += __shfl_xor_sync(0xffffffffu, po, 16);
        float o = dsm[FCB_OFF] + po;

        __syncwarp();
        // rebuild packed h from the warp's buffer
#pragma unroll
        for (int q = 0; q < 8; q++) {
            ulonglong2 hv = rb2[q];
            hp[2 * q + 0] = hv.x;
            hp[2 * q + 1] = hv.y;
        }
        __syncwarp();

        if (s == 0) out[(size_t)t * B + b] = o;
        if (t < TDEC - 1) {
            float4 yn = *(const float4*)(y + (size_t)b * 52 + (t + 1) * 4);
            xA = yn.y; xB = yn.z; xC = yn.w; xD = o;
        }
    }
}

extern "C" void kernel_launch(void* const* d_in, const int* in_sizes, int n_in,
                              void* d_out, int out_size) {
    const float* y      = (const float*)d_in[0];
    const float* enc    = (const float*)d_in[1];
    const float* hidden = (const float*)d_in[2];
    // d_in[3] = batch_ids (unused)
    const float* attn_W = (const float*)d_in[4];
    const float* attn_b = (const float*)d_in[5];
    const float* comb_W = (const float*)d_in[6];
    const float* comb_b = (const float*)d_in[7];
    const float* w_ih   = (const float*)d_in[8];
    const float* w_hh   = (const float*)d_in[9];
    const float* b_ih   = (const float*)d_in[10];
    const float* b_hh   = (const float*)d_in[11];
    const float* fc_W   = (const float*)d_in[12];
    const float* fc_b   = (const float*)d_in[13];

    const int smem_bytes = SMEM_FLOATS * 4;
    cudaFuncSetAttribute(decoder_loop, cudaFuncAttributeMaxDynamicSharedMemorySize,
                         smem_bytes);

    precompute_P<<<(48 * B) / 64, 256>>>(enc, comb_W);
    decoder_loop<<<B / 64, 256, smem_bytes>>>(y, hidden, attn_W, attn_b, comb_W,
                                              comb_b, w_ih, w_hh, b_ih, b_hh,
                                              fc_W, fc_b, (float*)d_out);
}